// round 15
// baseline (speedup 1.0000x reference)
#include <cuda_runtime.h>
#include <cuda_bf16.h>
#include <cuda_fp16.h>
#include <math_constants.h>

#define VV 3
#define BB 2
#define CC 16
#define HH 128
#define WW 128
#define DD 32
#define HWSZ (HH*WW)
#define NQ 4
#define NCH 8                      // depth chunks
#define DCH (DD/NCH)               // 4 depths per chunk
#define TS 16
#define THALO 20

// Scratch (device globals; no runtime allocation)
__device__ float g_proj[(VV-1)*BB*12];
__device__ float4 g_feat[(size_t)BB*NQ*HWSZ];           // fp32 chunk-planar, REF views only
// fp16 interleaved: 32B record per pixel -> both halves share a cache line
__device__ uint4 g_feath[(size_t)VV*BB*HWSZ*2];
__device__ float g_cost[(size_t)BB*DD*HWSZ];            // min cost volume
__device__ float g_wfeat[(size_t)25*BB*HWSZ];           // [k][b][pix]
__device__ float g_part[(size_t)BB*NCH*3*HWSZ];         // partial softmax (m,S,T)

// ---------------------------------------------------------------------------
// proj helpers (device, double precision)
// ---------------------------------------------------------------------------
__device__ void mat3_inv_d(const double* A, double* o) {
    double c00 = A[4]*A[8]-A[5]*A[7];
    double c01 = A[5]*A[6]-A[3]*A[8];
    double c02 = A[3]*A[7]-A[4]*A[6];
    double det = A[0]*c00 + A[1]*c01 + A[2]*c02;
    double id = 1.0/det;
    o[0]=c00*id;                  o[1]=(A[2]*A[7]-A[1]*A[8])*id; o[2]=(A[1]*A[5]-A[2]*A[4])*id;
    o[3]=c01*id;                  o[4]=(A[0]*A[8]-A[2]*A[6])*id; o[5]=(A[2]*A[3]-A[0]*A[5])*id;
    o[6]=c02*id;                  o[7]=(A[1]*A[6]-A[0]*A[7])*id; o[8]=(A[0]*A[4]-A[1]*A[3])*id;
}

__device__ void build_M(const float* intr, const float* c2w, int vb,
                        double* Afull, double* bfull) {
    double K[9], R[9], t[3];
    #pragma unroll
    for (int i = 0; i < 3; i++) {
        #pragma unroll
        for (int j = 0; j < 3; j++) {
            K[i*3+j] = (double)intr[(vb*3+i)*3+j];
            R[i*3+j] = (double)c2w[(vb*4+i)*4+j];
        }
        t[i] = (double)c2w[(vb*4+i)*4+3];
    }
    double bb[3];
    #pragma unroll
    for (int i = 0; i < 3; i++)
        bb[i] = -(R[0*3+i]*t[0] + R[1*3+i]*t[1] + R[2*3+i]*t[2]);
    #pragma unroll
    for (int i = 0; i < 3; i++) {
        #pragma unroll
        for (int j = 0; j < 3; j++)
            Afull[i*3+j] = K[i*3+0]*R[j*3+0] + K[i*3+1]*R[j*3+1] + K[i*3+2]*R[j*3+2];
        bfull[i] = K[i*3+0]*bb[0] + K[i*3+1]*bb[1] + K[i*3+2]*bb[2] + bb[i];
    }
}

__device__ void do_proj(const float* intr, const float* c2w, int t) {
    int v = t / BB + 1;
    int b = t % BB;

    double As[9], bs[3], Ar[9], br[3];
    build_M(intr, c2w, v*BB + b, As, bs);
    build_M(intr, c2w, 0*BB + b, Ar, br);

    double Ainv[9];
    mat3_inv_d(Ar, Ainv);
    double binv[3];
    #pragma unroll
    for (int i = 0; i < 3; i++)
        binv[i] = -(Ainv[i*3+0]*br[0] + Ainv[i*3+1]*br[1] + Ainv[i*3+2]*br[2]);

    float* P = g_proj + t*12;
    #pragma unroll
    for (int i = 0; i < 3; i++) {
        #pragma unroll
        for (int j = 0; j < 3; j++)
            P[i*3+j] = (float)(As[i*3+0]*Ainv[0*3+j] + As[i*3+1]*Ainv[1*3+j] + As[i*3+2]*Ainv[2*3+j]);
        P[9+i] = (float)(As[i*3+0]*binv[0] + As[i*3+1]*binv[1] + As[i*3+2]*binv[2] + bs[i]);
    }
}

// ---------------------------------------------------------------------------
// K1: transpose features -> fp16 interleaved records + fp32 planes (ref only)
// ---------------------------------------------------------------------------
__global__ void nhwc_kernel(const float* __restrict__ feat,
                            const float* __restrict__ intr,
                            const float* __restrict__ c2w) {
    if (blockIdx.x == 0 && threadIdx.x < (VV-1)*BB)
        do_proj(intr, c2w, threadIdx.x);

    int idx = blockIdx.x * blockDim.x + threadIdx.x;
    if (idx >= VV*BB*HWSZ) return;
    int pix = idx & (HWSZ-1);
    int vb  = idx >> 14;
    const float* in = feat + (size_t)vb*CC*HWSZ + pix;
    float v[16];
    #pragma unroll
    for (int c = 0; c < 16; c++) v[c] = in[(size_t)c*HWSZ];

    if (vb < BB) {
        #pragma unroll
        for (int q = 0; q < NQ; q++)
            g_feat[((size_t)(vb*NQ + q))*HWSZ + pix] =
                make_float4(v[q*4+0], v[q*4+1], v[q*4+2], v[q*4+3]);
    }

    #pragma unroll
    for (int q2 = 0; q2 < 2; q2++) {
        __half2 h0 = __floats2half2_rn(v[q2*8+0], v[q2*8+1]);
        __half2 h1 = __floats2half2_rn(v[q2*8+2], v[q2*8+3]);
        __half2 h2 = __floats2half2_rn(v[q2*8+4], v[q2*8+5]);
        __half2 h3 = __floats2half2_rn(v[q2*8+6], v[q2*8+7]);
        uint4 raw;
        raw.x = *reinterpret_cast<unsigned int*>(&h0);
        raw.y = *reinterpret_cast<unsigned int*>(&h1);
        raw.z = *reinterpret_cast<unsigned int*>(&h2);
        raw.w = *reinterpret_cast<unsigned int*>(&h3);
        // interleaved: record for pixel = 2 consecutive uint4
        g_feath[((size_t)vb*HWSZ + pix)*2 + q2] = raw;
    }
}

// ---------------------------------------------------------------------------
// K2: feature weights, smem-tiled (fp32, ref view)
// ---------------------------------------------------------------------------
__global__ void __launch_bounds__(256)
wfeat_kernel() {
    __shared__ float4 sf[NQ][THALO*THALO];

    int bx = blockIdx.x, by = blockIdx.y, b = blockIdx.z;
    int tid = threadIdx.x;
    int tx = tid & (TS-1), ty = tid >> 4;

    int ox = bx*TS - 2, oy = by*TS - 2;

    for (int i = tid; i < THALO*THALO; i += 256) {
        int ly = i / THALO, lx = i - ly*THALO;
        int gy = oy + ly, gx = ox + lx;
        if ((unsigned)gy < (unsigned)HH && (unsigned)gx < (unsigned)WW) {
            int gp = (gy<<7) + gx;
            #pragma unroll
            for (int q = 0; q < NQ; q++)
                sf[q][i] = g_feat[((size_t)(b*NQ + q))*HWSZ + gp];
        }
    }
    __syncthreads();

    int x = bx*TS + tx, y = by*TS + ty;
    int pix = (y<<7) + x;
    int lc = (ty+2)*THALO + (tx+2);

    float fc[16];
    #pragma unroll
    for (int q = 0; q < NQ; q++) {
        float4 a = sf[q][lc];
        fc[q*4+0]=a.x; fc[q*4+1]=a.y; fc[q*4+2]=a.z; fc[q*4+3]=a.w;
    }

    #pragma unroll
    for (int k = 0; k < 25; k++) {
        int di = k/5, dj = k%5;
        int ny = y + di - 2, nx = x + dj - 2;
        float w = 0.0f;
        if ((unsigned)ny < (unsigned)HH && (unsigned)nx < (unsigned)WW) {
            int ln = (ty+di)*THALO + (tx+dj);
            float s = 0.0f;
            #pragma unroll
            for (int q = 0; q < NQ; q++) {
                float4 c = sf[q][ln];
                float d0 = fc[q*4+0]-c.x, d1 = fc[q*4+1]-c.y;
                float d2 = fc[q*4+2]-c.z, d3 = fc[q*4+3]-c.w;
                s += d0*d0 + d1*d1 + d2*d2 + d3*d3;
            }
            w = sqrtf(s);
        }
        g_wfeat[((size_t)k*BB + b)*HWSZ + pix] = w;
    }
}

// ---------------------------------------------------------------------------
// K3: warp + bilinear (half2 HFMA2), 2 depths/thread, interleaved records
// ---------------------------------------------------------------------------
__global__ void __launch_bounds__(256, 5)
warp_cost_kernel(const float* __restrict__ depth_hypo) {
    int t = blockIdx.x * blockDim.x + threadIdx.x;     // over B * (D/2) * HWSZ
    if (t >= BB*(DD/2)*HWSZ) return;
    int pix = t & (HWSZ-1);
    int d2  = (t >> 14) & 15;
    int b   = t >> 18;
    int x = pix & 127, y = pix >> 7;

    int idx0 = ((b*DD + d2) << 14) | pix;
    int idx1 = idx0 + (16 << 14);
    float dep[2] = {depth_hypo[idx0], depth_hypo[idx1]};

    __half2 rv[8];
    {
        uint4 r0 = g_feath[((size_t)b*HWSZ + pix)*2 + 0];
        uint4 r1 = g_feath[((size_t)b*HWSZ + pix)*2 + 1];
        rv[0] = *reinterpret_cast<__half2*>(&r0.x);
        rv[1] = *reinterpret_cast<__half2*>(&r0.y);
        rv[2] = *reinterpret_cast<__half2*>(&r0.z);
        rv[3] = *reinterpret_cast<__half2*>(&r0.w);
        rv[4] = *reinterpret_cast<__half2*>(&r1.x);
        rv[5] = *reinterpret_cast<__half2*>(&r1.y);
        rv[6] = *reinterpret_cast<__half2*>(&r1.z);
        rv[7] = *reinterpret_cast<__half2*>(&r1.w);
    }

    const float SXY = (float)WW / (float)(WW-1);
    float fxp = (float)x, fyp = (float)y;

    __half2 cum[2][8];
    #pragma unroll
    for (int p = 0; p < 2; p++)
        #pragma unroll
        for (int j = 0; j < 8; j++) cum[p][j] = __float2half2_rn(0.0f);

    float cmin[2] = {CUDART_INF_F, CUDART_INF_F};

    #pragma unroll
    for (int v = 0; v < VV-1; v++) {
        const float* P = g_proj + (v*BB + b)*12;
        float rx = P[0]*fxp + P[1]*fyp + P[2];
        float ry = P[3]*fxp + P[4]*fyp + P[5];
        float rz = P[6]*fxp + P[7]*fyp + P[8];
        const uint4* sbh = g_feath + ((size_t)((v+1)*BB + b))*HWSZ*2;

        #pragma unroll
        for (int p = 0; p < 2; p++) {
            float depth = dep[p];
            float px = __fdividef(rx*depth + P[9],  rz*depth + P[11]) * SXY - 0.5f;
            float py = __fdividef(ry*depth + P[10], rz*depth + P[11]) * SXY - 0.5f;
            float x0f = floorf(px), y0f = floorf(py);
            float tx = px - x0f, ty = py - y0f;
            int x0 = (int)x0f, y0 = (int)y0f;

            #pragma unroll
            for (int tap = 0; tap < 4; tap++) {
                int xi = x0 + (tap & 1);
                int yi = y0 + (tap >> 1);
                if ((unsigned)xi < (unsigned)WW && (unsigned)yi < (unsigned)HH) {
                    float wx = (tap & 1)  ? tx : 1.0f - tx;
                    float wy = (tap >> 1) ? ty : 1.0f - ty;
                    __half2 wh = __float2half2_rn(wx * wy);
                    int sp = (yi<<7) + xi;
                    uint4 raw0 = sbh[sp*2 + 0];      // same 128B line as raw1
                    uint4 raw1 = sbh[sp*2 + 1];
                    cum[p][0] = __hfma2(wh, *reinterpret_cast<__half2*>(&raw0.x), cum[p][0]);
                    cum[p][1] = __hfma2(wh, *reinterpret_cast<__half2*>(&raw0.y), cum[p][1]);
                    cum[p][2] = __hfma2(wh, *reinterpret_cast<__half2*>(&raw0.z), cum[p][2]);
                    cum[p][3] = __hfma2(wh, *reinterpret_cast<__half2*>(&raw0.w), cum[p][3]);
                    cum[p][4] = __hfma2(wh, *reinterpret_cast<__half2*>(&raw1.x), cum[p][4]);
                    cum[p][5] = __hfma2(wh, *reinterpret_cast<__half2*>(&raw1.y), cum[p][5]);
                    cum[p][6] = __hfma2(wh, *reinterpret_cast<__half2*>(&raw1.z), cum[p][6]);
                    cum[p][7] = __hfma2(wh, *reinterpret_cast<__half2*>(&raw1.w), cum[p][7]);
                }
            }
        }

        #pragma unroll
        for (int p = 0; p < 2; p++) {
            float s = 0.0f;
            #pragma unroll
            for (int j = 0; j < 8; j++) {
                float2 f = __half22float2(__hsub2(rv[j], cum[p][j]));
                s += f.x*f.x + f.y*f.y;
            }
            cmin[p] = fminf(cmin[p], sqrtf(s));
        }
    }
    g_cost[idx0] = cmin[0];
    g_cost[idx1] = cmin[1];
}

// ---------------------------------------------------------------------------
// K4: tile x DCH-depth chunk (round-10 proven form: float2 smem, k-outer)
// ---------------------------------------------------------------------------
__global__ void __launch_bounds__(256, 6)
agg_part_kernel(const float* __restrict__ depth_hypo) {
    __shared__ float2 sdc[DCH][THALO*THALO];   // (depth, cost)

    int bx = blockIdx.x, by = blockIdx.y, bz = blockIdx.z;  // bz over B*NCH
    int b = bz >> 3, ch = bz & (NCH-1);
    int tid = threadIdx.x;
    int tx = tid & (TS-1), ty = tid >> 4;

    int x = bx*TS + tx, y = by*TS + ty;
    int pix = (y<<7) + x;
    int ox = bx*TS - 2, oy = by*TS - 2;

    const float* dbase = depth_hypo + (size_t)(b*DD + ch*DCH)*HWSZ;
    const float* cbase = g_cost     + (size_t)(b*DD + ch*DCH)*HWSZ;
    for (int i = tid; i < DCH*THALO*THALO; i += 256) {
        int dd = i / (THALO*THALO);
        int j  = i - dd*(THALO*THALO);
        int ly = j / THALO, lx = j - ly*THALO;
        int gy = oy + ly, gx = ox + lx;
        bool inb = (unsigned)gy < (unsigned)HH && (unsigned)gx < (unsigned)WW;
        int gp = (gy<<7) + gx;
        float dv = inb ? dbase[(size_t)dd*HWSZ + gp] : 0.0f;
        float cv = inb ? cbase[(size_t)dd*HWSZ + gp] : 0.0f;
        sdc[dd][j] = make_float2(dv, cv);
    }
    __syncthreads();

    int lc = (ty+2)*THALO + (tx+2);
    float dc[DCH], esum[DCH], acc[DCH];
    #pragma unroll
    for (int dd = 0; dd < DCH; dd++) {
        dc[dd] = sdc[dd][lc].x;
        esum[dd] = 0.0f;
        acc[dd] = 0.0f;
    }

    const float* wfb = g_wfeat + (size_t)b*HWSZ + pix;

    #pragma unroll
    for (int k = 0; k < 25; k++) {
        int di = k/5, dj = k%5;
        int ny = y + di - 2, nx = x + dj - 2;
        bool inb = (unsigned)ny < (unsigned)HH && (unsigned)nx < (unsigned)WW;
        int ln = (ty+di)*THALO + (tx+dj);
        float wf_k = inb ? wfb[(size_t)k * (BB*HWSZ)] : 0.0f;
        #pragma unroll
        for (int dd = 0; dd < DCH; dd++) {
            float2 v = sdc[dd][ln];
            float e = __expf(fabsf(v.x - dc[dd]));
            esum[dd] += e;
            acc[dd]  += v.y * e * wf_k;
        }
    }

    float m = -CUDART_INF_F, ss = 0.0f, ts = 0.0f;
    #pragma unroll
    for (int dd = 0; dd < DCH; dd++) {
        float agg = __fdividef(acc[dd], esum[dd]);
        float nm = fmaxf(m, agg);
        float scale = __expf(m - nm);
        float ea = __expf(agg - nm);
        ss = ss * scale + ea;
        ts = ts * scale + ea * dc[dd];
        m = nm;
    }

    size_t base = (size_t)bz*3*HWSZ + pix;
    g_part[base + 0*HWSZ] = m;
    g_part[base + 1*HWSZ] = ss;
    g_part[base + 2*HWSZ] = ts;
}

// ---------------------------------------------------------------------------
// K5: combine NCH chunk partials -> depth expectation
// ---------------------------------------------------------------------------
__global__ void __launch_bounds__(256)
combine_kernel(float* __restrict__ out) {
    int idx = blockIdx.x * blockDim.x + threadIdx.x;
    if (idx >= BB*HWSZ) return;
    int pix = idx & (HWSZ-1);
    int b   = idx >> 14;

    float mv[NCH], sv[NCH], tv[NCH];
    float M = -CUDART_INF_F;
    #pragma unroll
    for (int c = 0; c < NCH; c++) {
        size_t base = (size_t)(b*NCH + c)*3*HWSZ + pix;
        mv[c] = g_part[base + 0*HWSZ];
        sv[c] = g_part[base + 1*HWSZ];
        tv[c] = g_part[base + 2*HWSZ];
        M = fmaxf(M, mv[c]);
    }
    float S = 0.0f, T = 0.0f;
    #pragma unroll
    for (int c = 0; c < NCH; c++) {
        float sc = __expf(mv[c] - M);
        S += sv[c] * sc;
        T += tv[c] * sc;
    }
    out[idx] = __fdividef(T, S);
}

// ---------------------------------------------------------------------------
extern "C" void kernel_launch(void* const* d_in, const int* in_sizes, int n_in,
                              void* d_out, int out_size) {
    const float* features   = (const float*)d_in[0];
    const float* intrinsics = (const float*)d_in[1];
    const float* cam2world  = (const float*)d_in[2];
    const float* depth_hypo = (const float*)d_in[3];
    float* out = (float*)d_out;

    {
        int n = VV*BB*HWSZ;
        nhwc_kernel<<<(n + 255)/256, 256>>>(features, intrinsics, cam2world);
    }
    {
        dim3 g(WW/TS, HH/TS, BB);
        wfeat_kernel<<<g, 256>>>();
    }
    {
        int n = BB*(DD/2)*HWSZ;
        warp_cost_kernel<<<(n + 255)/256, 256>>>(depth_hypo);
    }
    {
        dim3 g(WW/TS, HH/TS, BB*NCH);
        agg_part_kernel<<<g, 256>>>(depth_hypo);
    }
    {
        int n = BB*HWSZ;
        combine_kernel<<<(n + 255)/256, 256>>>(out);
    }
}

// round 16
// speedup vs baseline: 1.0746x; 1.0746x over previous
#include <cuda_runtime.h>
#include <cuda_bf16.h>
#include <cuda_fp16.h>
#include <math_constants.h>

#define VV 3
#define BB 2
#define CC 16
#define HH 128
#define WW 128
#define DD 32
#define HWSZ (HH*WW)
#define NQ 4
#define NCH 8                      // depth chunks
#define DCH (DD/NCH)               // 4 depths per chunk
#define TS 16
#define THALO 20

// Scratch (device globals; no runtime allocation)
__device__ float g_proj[(VV-1)*BB*12];
__device__ float4 g_feat[(size_t)BB*NQ*HWSZ];           // fp32 chunk-planar, REF views only
__device__ uint4 g_feath[(size_t)VV*BB*2*HWSZ];         // fp16 chunk-planar (planar: best measured)
__device__ float g_cost[(size_t)BB*DD*HWSZ];            // min cost volume
__device__ float g_wfeat[(size_t)25*BB*HWSZ];           // [k][b][pix]
__device__ float g_part[(size_t)BB*NCH*3*HWSZ];         // partial softmax (m,S,T)

// ---------------------------------------------------------------------------
// proj helpers (device, double precision)
// ---------------------------------------------------------------------------
__device__ void mat3_inv_d(const double* A, double* o) {
    double c00 = A[4]*A[8]-A[5]*A[7];
    double c01 = A[5]*A[6]-A[3]*A[8];
    double c02 = A[3]*A[7]-A[4]*A[6];
    double det = A[0]*c00 + A[1]*c01 + A[2]*c02;
    double id = 1.0/det;
    o[0]=c00*id;                  o[1]=(A[2]*A[7]-A[1]*A[8])*id; o[2]=(A[1]*A[5]-A[2]*A[4])*id;
    o[3]=c01*id;                  o[4]=(A[0]*A[8]-A[2]*A[6])*id; o[5]=(A[2]*A[3]-A[0]*A[5])*id;
    o[6]=c02*id;                  o[7]=(A[1]*A[6]-A[0]*A[7])*id; o[8]=(A[0]*A[4]-A[1]*A[3])*id;
}

__device__ void build_M(const float* intr, const float* c2w, int vb,
                        double* Afull, double* bfull) {
    double K[9], R[9], t[3];
    #pragma unroll
    for (int i = 0; i < 3; i++) {
        #pragma unroll
        for (int j = 0; j < 3; j++) {
            K[i*3+j] = (double)intr[(vb*3+i)*3+j];
            R[i*3+j] = (double)c2w[(vb*4+i)*4+j];
        }
        t[i] = (double)c2w[(vb*4+i)*4+3];
    }
    double bb[3];
    #pragma unroll
    for (int i = 0; i < 3; i++)
        bb[i] = -(R[0*3+i]*t[0] + R[1*3+i]*t[1] + R[2*3+i]*t[2]);
    #pragma unroll
    for (int i = 0; i < 3; i++) {
        #pragma unroll
        for (int j = 0; j < 3; j++)
            Afull[i*3+j] = K[i*3+0]*R[j*3+0] + K[i*3+1]*R[j*3+1] + K[i*3+2]*R[j*3+2];
        bfull[i] = K[i*3+0]*bb[0] + K[i*3+1]*bb[1] + K[i*3+2]*bb[2] + bb[i];
    }
}

__device__ void do_proj(const float* intr, const float* c2w, int t) {
    int v = t / BB + 1;
    int b = t % BB;

    double As[9], bs[3], Ar[9], br[3];
    build_M(intr, c2w, v*BB + b, As, bs);
    build_M(intr, c2w, 0*BB + b, Ar, br);

    double Ainv[9];
    mat3_inv_d(Ar, Ainv);
    double binv[3];
    #pragma unroll
    for (int i = 0; i < 3; i++)
        binv[i] = -(Ainv[i*3+0]*br[0] + Ainv[i*3+1]*br[1] + Ainv[i*3+2]*br[2]);

    float* P = g_proj + t*12;
    #pragma unroll
    for (int i = 0; i < 3; i++) {
        #pragma unroll
        for (int j = 0; j < 3; j++)
            P[i*3+j] = (float)(As[i*3+0]*Ainv[0*3+j] + As[i*3+1]*Ainv[1*3+j] + As[i*3+2]*Ainv[2*3+j]);
        P[9+i] = (float)(As[i*3+0]*binv[0] + As[i*3+1]*binv[1] + As[i*3+2]*binv[2] + bs[i]);
    }
}

// ---------------------------------------------------------------------------
// K1: transpose features -> fp16 chunk-planar (all) + fp32 (ref views only)
// ---------------------------------------------------------------------------
__global__ void nhwc_kernel(const float* __restrict__ feat,
                            const float* __restrict__ intr,
                            const float* __restrict__ c2w) {
    if (blockIdx.x == 0 && threadIdx.x < (VV-1)*BB)
        do_proj(intr, c2w, threadIdx.x);

    int idx = blockIdx.x * blockDim.x + threadIdx.x;
    if (idx >= VV*BB*HWSZ) return;
    int pix = idx & (HWSZ-1);
    int vb  = idx >> 14;
    const float* in = feat + (size_t)vb*CC*HWSZ + pix;
    float v[16];
    #pragma unroll
    for (int c = 0; c < 16; c++) v[c] = in[(size_t)c*HWSZ];

    if (vb < BB) {
        #pragma unroll
        for (int q = 0; q < NQ; q++)
            g_feat[((size_t)(vb*NQ + q))*HWSZ + pix] =
                make_float4(v[q*4+0], v[q*4+1], v[q*4+2], v[q*4+3]);
    }

    #pragma unroll
    for (int q2 = 0; q2 < 2; q2++) {
        __half2 h0 = __floats2half2_rn(v[q2*8+0], v[q2*8+1]);
        __half2 h1 = __floats2half2_rn(v[q2*8+2], v[q2*8+3]);
        __half2 h2 = __floats2half2_rn(v[q2*8+4], v[q2*8+5]);
        __half2 h3 = __floats2half2_rn(v[q2*8+6], v[q2*8+7]);
        uint4 raw;
        raw.x = *reinterpret_cast<unsigned int*>(&h0);
        raw.y = *reinterpret_cast<unsigned int*>(&h1);
        raw.z = *reinterpret_cast<unsigned int*>(&h2);
        raw.w = *reinterpret_cast<unsigned int*>(&h3);
        g_feath[((size_t)(vb*2 + q2))*HWSZ + pix] = raw;
    }
}

// ---------------------------------------------------------------------------
// K2: feature weights, smem-tiled (fp32, ref view)
// ---------------------------------------------------------------------------
__global__ void __launch_bounds__(256)
wfeat_kernel() {
    __shared__ float4 sf[NQ][THALO*THALO];

    int bx = blockIdx.x, by = blockIdx.y, b = blockIdx.z;
    int tid = threadIdx.x;
    int tx = tid & (TS-1), ty = tid >> 4;

    int ox = bx*TS - 2, oy = by*TS - 2;

    for (int i = tid; i < THALO*THALO; i += 256) {
        int ly = i / THALO, lx = i - ly*THALO;
        int gy = oy + ly, gx = ox + lx;
        if ((unsigned)gy < (unsigned)HH && (unsigned)gx < (unsigned)WW) {
            int gp = (gy<<7) + gx;
            #pragma unroll
            for (int q = 0; q < NQ; q++)
                sf[q][i] = g_feat[((size_t)(b*NQ + q))*HWSZ + gp];
        }
    }
    __syncthreads();

    int x = bx*TS + tx, y = by*TS + ty;
    int pix = (y<<7) + x;
    int lc = (ty+2)*THALO + (tx+2);

    float fc[16];
    #pragma unroll
    for (int q = 0; q < NQ; q++) {
        float4 a = sf[q][lc];
        fc[q*4+0]=a.x; fc[q*4+1]=a.y; fc[q*4+2]=a.z; fc[q*4+3]=a.w;
    }

    #pragma unroll
    for (int k = 0; k < 25; k++) {
        int di = k/5, dj = k%5;
        int ny = y + di - 2, nx = x + dj - 2;
        float w = 0.0f;
        if ((unsigned)ny < (unsigned)HH && (unsigned)nx < (unsigned)WW) {
            int ln = (ty+di)*THALO + (tx+dj);
            float s = 0.0f;
            #pragma unroll
            for (int q = 0; q < NQ; q++) {
                float4 c = sf[q][ln];
                float d0 = fc[q*4+0]-c.x, d1 = fc[q*4+1]-c.y;
                float d2 = fc[q*4+2]-c.z, d3 = fc[q*4+3]-c.w;
                s += d0*d0 + d1*d1 + d2*d2 + d3*d3;
            }
            w = sqrtf(s);
        }
        g_wfeat[((size_t)k*BB + b)*HWSZ + pix] = w;
    }
}

// ---------------------------------------------------------------------------
// K3: warp + bilinear (half2 HFMA2), 2 depths/thread.
//     Predicated taps: clamp coords, load unconditionally, weight *= validity.
//     (0-weight HFMA2 adds exactly 0 -> result identical to branchy version.)
// ---------------------------------------------------------------------------
__global__ void __launch_bounds__(256, 5)
warp_cost_kernel(const float* __restrict__ depth_hypo) {
    int t = blockIdx.x * blockDim.x + threadIdx.x;     // over B * (D/2) * HWSZ
    if (t >= BB*(DD/2)*HWSZ) return;
    int pix = t & (HWSZ-1);
    int d2  = (t >> 14) & 15;
    int b   = t >> 18;
    int x = pix & 127, y = pix >> 7;

    int idx0 = ((b*DD + d2) << 14) | pix;
    int idx1 = idx0 + (16 << 14);
    float dep[2] = {depth_hypo[idx0], depth_hypo[idx1]};

    __half2 rv[8];
    {
        uint4 r0 = g_feath[(size_t)(b*2+0)*HWSZ + pix];
        uint4 r1 = g_feath[(size_t)(b*2+1)*HWSZ + pix];
        rv[0] = *reinterpret_cast<__half2*>(&r0.x);
        rv[1] = *reinterpret_cast<__half2*>(&r0.y);
        rv[2] = *reinterpret_cast<__half2*>(&r0.z);
        rv[3] = *reinterpret_cast<__half2*>(&r0.w);
        rv[4] = *reinterpret_cast<__half2*>(&r1.x);
        rv[5] = *reinterpret_cast<__half2*>(&r1.y);
        rv[6] = *reinterpret_cast<__half2*>(&r1.z);
        rv[7] = *reinterpret_cast<__half2*>(&r1.w);
    }

    const float SXY = (float)WW / (float)(WW-1);
    float fxp = (float)x, fyp = (float)y;

    __half2 cum[2][8];
    #pragma unroll
    for (int p = 0; p < 2; p++)
        #pragma unroll
        for (int j = 0; j < 8; j++) cum[p][j] = __float2half2_rn(0.0f);

    float cmin[2] = {CUDART_INF_F, CUDART_INF_F};

    #pragma unroll
    for (int v = 0; v < VV-1; v++) {
        const float* P = g_proj + (v*BB + b)*12;
        float rx = P[0]*fxp + P[1]*fyp + P[2];
        float ry = P[3]*fxp + P[4]*fyp + P[5];
        float rz = P[6]*fxp + P[7]*fyp + P[8];
        const uint4* sbh = g_feath + ((size_t)((v+1)*BB + b)*2)*HWSZ;

        #pragma unroll
        for (int p = 0; p < 2; p++) {
            float depth = dep[p];
            float px = __fdividef(rx*depth + P[9],  rz*depth + P[11]) * SXY - 0.5f;
            float py = __fdividef(ry*depth + P[10], rz*depth + P[11]) * SXY - 0.5f;
            float x0f = floorf(px), y0f = floorf(py);
            float tx = px - x0f, ty = py - y0f;
            int x0 = (int)x0f, y0 = (int)y0f;

            #pragma unroll
            for (int tap = 0; tap < 4; tap++) {
                int xi = x0 + (tap & 1);
                int yi = y0 + (tap >> 1);
                // predicated: clamp + validity-weight instead of branch
                bool valid = ((unsigned)xi < (unsigned)WW) & ((unsigned)yi < (unsigned)HH);
                int xc = min(max(xi, 0), WW-1);
                int yc = min(max(yi, 0), HH-1);
                float wx = (tap & 1)  ? tx : 1.0f - tx;
                float wy = (tap >> 1) ? ty : 1.0f - ty;
                float w = valid ? wx * wy : 0.0f;
                __half2 wh = __float2half2_rn(w);
                int sp = (yc<<7) + xc;
                uint4 raw0 = sbh[sp];
                uint4 raw1 = sbh[(size_t)HWSZ + sp];
                cum[p][0] = __hfma2(wh, *reinterpret_cast<__half2*>(&raw0.x), cum[p][0]);
                cum[p][1] = __hfma2(wh, *reinterpret_cast<__half2*>(&raw0.y), cum[p][1]);
                cum[p][2] = __hfma2(wh, *reinterpret_cast<__half2*>(&raw0.z), cum[p][2]);
                cum[p][3] = __hfma2(wh, *reinterpret_cast<__half2*>(&raw0.w), cum[p][3]);
                cum[p][4] = __hfma2(wh, *reinterpret_cast<__half2*>(&raw1.x), cum[p][4]);
                cum[p][5] = __hfma2(wh, *reinterpret_cast<__half2*>(&raw1.y), cum[p][5]);
                cum[p][6] = __hfma2(wh, *reinterpret_cast<__half2*>(&raw1.z), cum[p][6]);
                cum[p][7] = __hfma2(wh, *reinterpret_cast<__half2*>(&raw1.w), cum[p][7]);
            }
        }

        #pragma unroll
        for (int p = 0; p < 2; p++) {
            float s = 0.0f;
            #pragma unroll
            for (int j = 0; j < 8; j++) {
                float2 f = __half22float2(__hsub2(rv[j], cum[p][j]));
                s += f.x*f.x + f.y*f.y;
            }
            cmin[p] = fminf(cmin[p], sqrtf(s));
        }
    }
    g_cost[idx0] = cmin[0];
    g_cost[idx1] = cmin[1];
}

// ---------------------------------------------------------------------------
// K4: tile x DCH-depth chunk (round-10 proven form: float2 smem, k-outer)
// ---------------------------------------------------------------------------
__global__ void __launch_bounds__(256, 6)
agg_part_kernel(const float* __restrict__ depth_hypo) {
    __shared__ float2 sdc[DCH][THALO*THALO];   // (depth, cost)

    int bx = blockIdx.x, by = blockIdx.y, bz = blockIdx.z;  // bz over B*NCH
    int b = bz >> 3, ch = bz & (NCH-1);
    int tid = threadIdx.x;
    int tx = tid & (TS-1), ty = tid >> 4;

    int x = bx*TS + tx, y = by*TS + ty;
    int pix = (y<<7) + x;
    int ox = bx*TS - 2, oy = by*TS - 2;

    const float* dbase = depth_hypo + (size_t)(b*DD + ch*DCH)*HWSZ;
    const float* cbase = g_cost     + (size_t)(b*DD + ch*DCH)*HWSZ;
    for (int i = tid; i < DCH*THALO*THALO; i += 256) {
        int dd = i / (THALO*THALO);
        int j  = i - dd*(THALO*THALO);
        int ly = j / THALO, lx = j - ly*THALO;
        int gy = oy + ly, gx = ox + lx;
        bool inb = (unsigned)gy < (unsigned)HH && (unsigned)gx < (unsigned)WW;
        int gp = (gy<<7) + gx;
        float dv = inb ? dbase[(size_t)dd*HWSZ + gp] : 0.0f;
        float cv = inb ? cbase[(size_t)dd*HWSZ + gp] : 0.0f;
        sdc[dd][j] = make_float2(dv, cv);
    }
    __syncthreads();

    int lc = (ty+2)*THALO + (tx+2);
    float dc[DCH], esum[DCH], acc[DCH];
    #pragma unroll
    for (int dd = 0; dd < DCH; dd++) {
        dc[dd] = sdc[dd][lc].x;
        esum[dd] = 0.0f;
        acc[dd] = 0.0f;
    }

    const float* wfb = g_wfeat + (size_t)b*HWSZ + pix;

    #pragma unroll
    for (int k = 0; k < 25; k++) {
        int di = k/5, dj = k%5;
        int ny = y + di - 2, nx = x + dj - 2;
        bool inb = (unsigned)ny < (unsigned)HH && (unsigned)nx < (unsigned)WW;
        int ln = (ty+di)*THALO + (tx+dj);
        float wf_k = inb ? wfb[(size_t)k * (BB*HWSZ)] : 0.0f;
        #pragma unroll
        for (int dd = 0; dd < DCH; dd++) {
            float2 v = sdc[dd][ln];
            float e = __expf(fabsf(v.x - dc[dd]));
            esum[dd] += e;
            acc[dd]  += v.y * e * wf_k;
        }
    }

    float m = -CUDART_INF_F, ss = 0.0f, ts = 0.0f;
    #pragma unroll
    for (int dd = 0; dd < DCH; dd++) {
        float agg = __fdividef(acc[dd], esum[dd]);
        float nm = fmaxf(m, agg);
        float scale = __expf(m - nm);
        float ea = __expf(agg - nm);
        ss = ss * scale + ea;
        ts = ts * scale + ea * dc[dd];
        m = nm;
    }

    size_t base = (size_t)bz*3*HWSZ + pix;
    g_part[base + 0*HWSZ] = m;
    g_part[base + 1*HWSZ] = ss;
    g_part[base + 2*HWSZ] = ts;
}

// ---------------------------------------------------------------------------
// K5: combine NCH chunk partials -> depth expectation
// ---------------------------------------------------------------------------
__global__ void __launch_bounds__(256)
combine_kernel(float* __restrict__ out) {
    int idx = blockIdx.x * blockDim.x + threadIdx.x;
    if (idx >= BB*HWSZ) return;
    int pix = idx & (HWSZ-1);
    int b   = idx >> 14;

    float mv[NCH], sv[NCH], tv[NCH];
    float M = -CUDART_INF_F;
    #pragma unroll
    for (int c = 0; c < NCH; c++) {
        size_t base = (size_t)(b*NCH + c)*3*HWSZ + pix;
        mv[c] = g_part[base + 0*HWSZ];
        sv[c] = g_part[base + 1*HWSZ];
        tv[c] = g_part[base + 2*HWSZ];
        M = fmaxf(M, mv[c]);
    }
    float S = 0.0f, T = 0.0f;
    #pragma unroll
    for (int c = 0; c < NCH; c++) {
        float sc = __expf(mv[c] - M);
        S += sv[c] * sc;
        T += tv[c] * sc;
    }
    out[idx] = __fdividef(T, S);
}

// ---------------------------------------------------------------------------
extern "C" void kernel_launch(void* const* d_in, const int* in_sizes, int n_in,
                              void* d_out, int out_size) {
    const float* features   = (const float*)d_in[0];
    const float* intrinsics = (const float*)d_in[1];
    const float* cam2world  = (const float*)d_in[2];
    const float* depth_hypo = (const float*)d_in[3];
    float* out = (float*)d_out;

    {
        int n = VV*BB*HWSZ;
        nhwc_kernel<<<(n + 255)/256, 256>>>(features, intrinsics, cam2world);
    }
    {
        dim3 g(WW/TS, HH/TS, BB);
        wfeat_kernel<<<g, 256>>>();
    }
    {
        int n = BB*(DD/2)*HWSZ;
        warp_cost_kernel<<<(n + 255)/256, 256>>>(depth_hypo);
    }
    {
        dim3 g(WW/TS, HH/TS, BB*NCH);
        agg_part_kernel<<<g, 256>>>(depth_hypo);
    }
    {
        int n = BB*HWSZ;
        combine_kernel<<<(n + 255)/256, 256>>>(out);
    }
}

// round 17
// speedup vs baseline: 1.1448x; 1.0654x over previous
#include <cuda_runtime.h>
#include <cuda_bf16.h>
#include <cuda_fp16.h>
#include <math_constants.h>

#define VV 3
#define BB 2
#define CC 16
#define HH 128
#define WW 128
#define DD 32
#define HWSZ (HH*WW)
#define NQ 4
#define NCH 8                      // depth chunks
#define DCH (DD/NCH)               // 4 depths per chunk
#define TS 16
#define THALO 20

// Scratch (device globals; no runtime allocation)
__device__ float g_proj[(VV-1)*BB*12];
__device__ float4 g_feat[(size_t)BB*NQ*HWSZ];           // fp32 chunk-planar, REF views only
__device__ uint4 g_feath[(size_t)VV*BB*2*HWSZ];         // fp16 chunk-planar
__device__ float g_cost[(size_t)BB*DD*HWSZ];            // min cost volume
__device__ float g_wfeat[(size_t)25*BB*HWSZ];           // [k][b][pix]
__device__ float g_part[(size_t)BB*NCH*3*HWSZ];         // partial softmax (m,S,T)

// ---------------------------------------------------------------------------
// proj helpers (device, double precision)
// ---------------------------------------------------------------------------
__device__ void mat3_inv_d(const double* A, double* o) {
    double c00 = A[4]*A[8]-A[5]*A[7];
    double c01 = A[5]*A[6]-A[3]*A[8];
    double c02 = A[3]*A[7]-A[4]*A[6];
    double det = A[0]*c00 + A[1]*c01 + A[2]*c02;
    double id = 1.0/det;
    o[0]=c00*id;                  o[1]=(A[2]*A[7]-A[1]*A[8])*id; o[2]=(A[1]*A[5]-A[2]*A[4])*id;
    o[3]=c01*id;                  o[4]=(A[0]*A[8]-A[2]*A[6])*id; o[5]=(A[2]*A[3]-A[0]*A[5])*id;
    o[6]=c02*id;                  o[7]=(A[1]*A[6]-A[0]*A[7])*id; o[8]=(A[0]*A[4]-A[1]*A[3])*id;
}

__device__ void build_M(const float* intr, const float* c2w, int vb,
                        double* Afull, double* bfull) {
    double K[9], R[9], t[3];
    #pragma unroll
    for (int i = 0; i < 3; i++) {
        #pragma unroll
        for (int j = 0; j < 3; j++) {
            K[i*3+j] = (double)intr[(vb*3+i)*3+j];
            R[i*3+j] = (double)c2w[(vb*4+i)*4+j];
        }
        t[i] = (double)c2w[(vb*4+i)*4+3];
    }
    double bb[3];
    #pragma unroll
    for (int i = 0; i < 3; i++)
        bb[i] = -(R[0*3+i]*t[0] + R[1*3+i]*t[1] + R[2*3+i]*t[2]);
    #pragma unroll
    for (int i = 0; i < 3; i++) {
        #pragma unroll
        for (int j = 0; j < 3; j++)
            Afull[i*3+j] = K[i*3+0]*R[j*3+0] + K[i*3+1]*R[j*3+1] + K[i*3+2]*R[j*3+2];
        bfull[i] = K[i*3+0]*bb[0] + K[i*3+1]*bb[1] + K[i*3+2]*bb[2] + bb[i];
    }
}

__device__ void do_proj(const float* intr, const float* c2w, int t) {
    int v = t / BB + 1;
    int b = t % BB;

    double As[9], bs[3], Ar[9], br[3];
    build_M(intr, c2w, v*BB + b, As, bs);
    build_M(intr, c2w, 0*BB + b, Ar, br);

    double Ainv[9];
    mat3_inv_d(Ar, Ainv);
    double binv[3];
    #pragma unroll
    for (int i = 0; i < 3; i++)
        binv[i] = -(Ainv[i*3+0]*br[0] + Ainv[i*3+1]*br[1] + Ainv[i*3+2]*br[2]);

    float* P = g_proj + t*12;
    #pragma unroll
    for (int i = 0; i < 3; i++) {
        #pragma unroll
        for (int j = 0; j < 3; j++)
            P[i*3+j] = (float)(As[i*3+0]*Ainv[0*3+j] + As[i*3+1]*Ainv[1*3+j] + As[i*3+2]*Ainv[2*3+j]);
        P[9+i] = (float)(As[i*3+0]*binv[0] + As[i*3+1]*binv[1] + As[i*3+2]*binv[2] + bs[i]);
    }
}

// ---------------------------------------------------------------------------
// K1: transpose features -> fp16 chunk-planar (all) + fp32 (ref views only)
// ---------------------------------------------------------------------------
__global__ void nhwc_kernel(const float* __restrict__ feat,
                            const float* __restrict__ intr,
                            const float* __restrict__ c2w) {
    if (blockIdx.x == 0 && threadIdx.x < (VV-1)*BB)
        do_proj(intr, c2w, threadIdx.x);

    int idx = blockIdx.x * blockDim.x + threadIdx.x;
    if (idx >= VV*BB*HWSZ) return;
    int pix = idx & (HWSZ-1);
    int vb  = idx >> 14;
    const float* in = feat + (size_t)vb*CC*HWSZ + pix;
    float v[16];
    #pragma unroll
    for (int c = 0; c < 16; c++) v[c] = in[(size_t)c*HWSZ];

    if (vb < BB) {
        #pragma unroll
        for (int q = 0; q < NQ; q++)
            g_feat[((size_t)(vb*NQ + q))*HWSZ + pix] =
                make_float4(v[q*4+0], v[q*4+1], v[q*4+2], v[q*4+3]);
    }

    #pragma unroll
    for (int q2 = 0; q2 < 2; q2++) {
        __half2 h0 = __floats2half2_rn(v[q2*8+0], v[q2*8+1]);
        __half2 h1 = __floats2half2_rn(v[q2*8+2], v[q2*8+3]);
        __half2 h2 = __floats2half2_rn(v[q2*8+4], v[q2*8+5]);
        __half2 h3 = __floats2half2_rn(v[q2*8+6], v[q2*8+7]);
        uint4 raw;
        raw.x = *reinterpret_cast<unsigned int*>(&h0);
        raw.y = *reinterpret_cast<unsigned int*>(&h1);
        raw.z = *reinterpret_cast<unsigned int*>(&h2);
        raw.w = *reinterpret_cast<unsigned int*>(&h3);
        g_feath[((size_t)(vb*2 + q2))*HWSZ + pix] = raw;
    }
}

// ---------------------------------------------------------------------------
// K2: feature weights, smem-tiled (fp32, ref view)
// ---------------------------------------------------------------------------
__global__ void __launch_bounds__(256)
wfeat_kernel() {
    __shared__ float4 sf[NQ][THALO*THALO];

    int bx = blockIdx.x, by = blockIdx.y, b = blockIdx.z;
    int tid = threadIdx.x;
    int tx = tid & (TS-1), ty = tid >> 4;

    int ox = bx*TS - 2, oy = by*TS - 2;

    for (int i = tid; i < THALO*THALO; i += 256) {
        int ly = i / THALO, lx = i - ly*THALO;
        int gy = oy + ly, gx = ox + lx;
        if ((unsigned)gy < (unsigned)HH && (unsigned)gx < (unsigned)WW) {
            int gp = (gy<<7) + gx;
            #pragma unroll
            for (int q = 0; q < NQ; q++)
                sf[q][i] = g_feat[((size_t)(b*NQ + q))*HWSZ + gp];
        }
    }
    __syncthreads();

    int x = bx*TS + tx, y = by*TS + ty;
    int pix = (y<<7) + x;
    int lc = (ty+2)*THALO + (tx+2);

    float fc[16];
    #pragma unroll
    for (int q = 0; q < NQ; q++) {
        float4 a = sf[q][lc];
        fc[q*4+0]=a.x; fc[q*4+1]=a.y; fc[q*4+2]=a.z; fc[q*4+3]=a.w;
    }

    #pragma unroll
    for (int k = 0; k < 25; k++) {
        int di = k/5, dj = k%5;
        int ny = y + di - 2, nx = x + dj - 2;
        float w = 0.0f;
        if ((unsigned)ny < (unsigned)HH && (unsigned)nx < (unsigned)WW) {
            int ln = (ty+di)*THALO + (tx+dj);
            float s = 0.0f;
            #pragma unroll
            for (int q = 0; q < NQ; q++) {
                float4 c = sf[q][ln];
                float d0 = fc[q*4+0]-c.x, d1 = fc[q*4+1]-c.y;
                float d2 = fc[q*4+2]-c.z, d3 = fc[q*4+3]-c.w;
                s += d0*d0 + d1*d1 + d2*d2 + d3*d3;
            }
            w = sqrtf(s);
        }
        g_wfeat[((size_t)k*BB + b)*HWSZ + pix] = w;
    }
}

// ---------------------------------------------------------------------------
// K3: warp + bilinear (half2 HFMA2), 2 depths/thread (r10 branchy form)
// ---------------------------------------------------------------------------
__global__ void __launch_bounds__(256, 5)
warp_cost_kernel(const float* __restrict__ depth_hypo) {
    int t = blockIdx.x * blockDim.x + threadIdx.x;     // over B * (D/2) * HWSZ
    if (t >= BB*(DD/2)*HWSZ) return;
    int pix = t & (HWSZ-1);
    int d2  = (t >> 14) & 15;
    int b   = t >> 18;
    int x = pix & 127, y = pix >> 7;

    int idx0 = ((b*DD + d2) << 14) | pix;
    int idx1 = idx0 + (16 << 14);
    float dep[2] = {depth_hypo[idx0], depth_hypo[idx1]};

    __half2 rv[8];
    {
        uint4 r0 = g_feath[(size_t)(b*2+0)*HWSZ + pix];
        uint4 r1 = g_feath[(size_t)(b*2+1)*HWSZ + pix];
        rv[0] = *reinterpret_cast<__half2*>(&r0.x);
        rv[1] = *reinterpret_cast<__half2*>(&r0.y);
        rv[2] = *reinterpret_cast<__half2*>(&r0.z);
        rv[3] = *reinterpret_cast<__half2*>(&r0.w);
        rv[4] = *reinterpret_cast<__half2*>(&r1.x);
        rv[5] = *reinterpret_cast<__half2*>(&r1.y);
        rv[6] = *reinterpret_cast<__half2*>(&r1.z);
        rv[7] = *reinterpret_cast<__half2*>(&r1.w);
    }

    const float SXY = (float)WW / (float)(WW-1);
    float fxp = (float)x, fyp = (float)y;

    __half2 cum[2][8];
    #pragma unroll
    for (int p = 0; p < 2; p++)
        #pragma unroll
        for (int j = 0; j < 8; j++) cum[p][j] = __float2half2_rn(0.0f);

    float cmin[2] = {CUDART_INF_F, CUDART_INF_F};

    #pragma unroll
    for (int v = 0; v < VV-1; v++) {
        const float* P = g_proj + (v*BB + b)*12;
        float rx = P[0]*fxp + P[1]*fyp + P[2];
        float ry = P[3]*fxp + P[4]*fyp + P[5];
        float rz = P[6]*fxp + P[7]*fyp + P[8];
        const uint4* sbh = g_feath + ((size_t)((v+1)*BB + b)*2)*HWSZ;

        #pragma unroll
        for (int p = 0; p < 2; p++) {
            float depth = dep[p];
            float px = __fdividef(rx*depth + P[9],  rz*depth + P[11]) * SXY - 0.5f;
            float py = __fdividef(ry*depth + P[10], rz*depth + P[11]) * SXY - 0.5f;
            float x0f = floorf(px), y0f = floorf(py);
            float tx = px - x0f, ty = py - y0f;
            int x0 = (int)x0f, y0 = (int)y0f;

            #pragma unroll
            for (int tap = 0; tap < 4; tap++) {
                int xi = x0 + (tap & 1);
                int yi = y0 + (tap >> 1);
                if ((unsigned)xi < (unsigned)WW && (unsigned)yi < (unsigned)HH) {
                    float wx = (tap & 1)  ? tx : 1.0f - tx;
                    float wy = (tap >> 1) ? ty : 1.0f - ty;
                    __half2 wh = __float2half2_rn(wx * wy);
                    int sp = (yi<<7) + xi;
                    uint4 raw0 = sbh[sp];
                    uint4 raw1 = sbh[(size_t)HWSZ + sp];
                    cum[p][0] = __hfma2(wh, *reinterpret_cast<__half2*>(&raw0.x), cum[p][0]);
                    cum[p][1] = __hfma2(wh, *reinterpret_cast<__half2*>(&raw0.y), cum[p][1]);
                    cum[p][2] = __hfma2(wh, *reinterpret_cast<__half2*>(&raw0.z), cum[p][2]);
                    cum[p][3] = __hfma2(wh, *reinterpret_cast<__half2*>(&raw0.w), cum[p][3]);
                    cum[p][4] = __hfma2(wh, *reinterpret_cast<__half2*>(&raw1.x), cum[p][4]);
                    cum[p][5] = __hfma2(wh, *reinterpret_cast<__half2*>(&raw1.y), cum[p][5]);
                    cum[p][6] = __hfma2(wh, *reinterpret_cast<__half2*>(&raw1.z), cum[p][6]);
                    cum[p][7] = __hfma2(wh, *reinterpret_cast<__half2*>(&raw1.w), cum[p][7]);
                }
            }
        }

        #pragma unroll
        for (int p = 0; p < 2; p++) {
            float s = 0.0f;
            #pragma unroll
            for (int j = 0; j < 8; j++) {
                float2 f = __half22float2(__hsub2(rv[j], cum[p][j]));
                s += f.x*f.x + f.y*f.y;
            }
            cmin[p] = fminf(cmin[p], sqrtf(s));
        }
    }
    g_cost[idx0] = cmin[0];
    g_cost[idx1] = cmin[1];
}

// ---------------------------------------------------------------------------
// K4: tile x DCH-depth chunk (float2 smem, k-outer) — (256,5) to avoid spills
// ---------------------------------------------------------------------------
__global__ void __launch_bounds__(256, 5)
agg_part_kernel(const float* __restrict__ depth_hypo) {
    __shared__ float2 sdc[DCH][THALO*THALO];   // (depth, cost)

    int bx = blockIdx.x, by = blockIdx.y, bz = blockIdx.z;  // bz over B*NCH
    int b = bz >> 3, ch = bz & (NCH-1);
    int tid = threadIdx.x;
    int tx = tid & (TS-1), ty = tid >> 4;

    int x = bx*TS + tx, y = by*TS + ty;
    int pix = (y<<7) + x;
    int ox = bx*TS - 2, oy = by*TS - 2;

    const float* dbase = depth_hypo + (size_t)(b*DD + ch*DCH)*HWSZ;
    const float* cbase = g_cost     + (size_t)(b*DD + ch*DCH)*HWSZ;
    for (int i = tid; i < DCH*THALO*THALO; i += 256) {
        int dd = i / (THALO*THALO);
        int j  = i - dd*(THALO*THALO);
        int ly = j / THALO, lx = j - ly*THALO;
        int gy = oy + ly, gx = ox + lx;
        bool inb = (unsigned)gy < (unsigned)HH && (unsigned)gx < (unsigned)WW;
        int gp = (gy<<7) + gx;
        float dv = inb ? dbase[(size_t)dd*HWSZ + gp] : 0.0f;
        float cv = inb ? cbase[(size_t)dd*HWSZ + gp] : 0.0f;
        sdc[dd][j] = make_float2(dv, cv);
    }
    __syncthreads();

    int lc = (ty+2)*THALO + (tx+2);
    float dc[DCH], esum[DCH], acc[DCH];
    #pragma unroll
    for (int dd = 0; dd < DCH; dd++) {
        dc[dd] = sdc[dd][lc].x;
        esum[dd] = 0.0f;
        acc[dd] = 0.0f;
    }

    const float* wfb = g_wfeat + (size_t)b*HWSZ + pix;

    #pragma unroll
    for (int k = 0; k < 25; k++) {
        int di = k/5, dj = k%5;
        int ny = y + di - 2, nx = x + dj - 2;
        bool inb = (unsigned)ny < (unsigned)HH && (unsigned)nx < (unsigned)WW;
        int ln = (ty+di)*THALO + (tx+dj);
        float wf_k = inb ? wfb[(size_t)k * (BB*HWSZ)] : 0.0f;
        #pragma unroll
        for (int dd = 0; dd < DCH; dd++) {
            float2 v = sdc[dd][ln];
            float e = __expf(fabsf(v.x - dc[dd]));
            esum[dd] += e;
            acc[dd]  += v.y * e * wf_k;
        }
    }

    float m = -CUDART_INF_F, ss = 0.0f, ts = 0.0f;
    #pragma unroll
    for (int dd = 0; dd < DCH; dd++) {
        float agg = __fdividef(acc[dd], esum[dd]);
        float nm = fmaxf(m, agg);
        float scale = __expf(m - nm);
        float ea = __expf(agg - nm);
        ss = ss * scale + ea;
        ts = ts * scale + ea * dc[dd];
        m = nm;
    }

    size_t base = (size_t)bz*3*HWSZ + pix;
    g_part[base + 0*HWSZ] = m;
    g_part[base + 1*HWSZ] = ss;
    g_part[base + 2*HWSZ] = ts;
}

// ---------------------------------------------------------------------------
// K5: combine NCH chunk partials -> depth expectation
// ---------------------------------------------------------------------------
__global__ void __launch_bounds__(256)
combine_kernel(float* __restrict__ out) {
    int idx = blockIdx.x * blockDim.x + threadIdx.x;
    if (idx >= BB*HWSZ) return;
    int pix = idx & (HWSZ-1);
    int b   = idx >> 14;

    float mv[NCH], sv[NCH], tv[NCH];
    float M = -CUDART_INF_F;
    #pragma unroll
    for (int c = 0; c < NCH; c++) {
        size_t base = (size_t)(b*NCH + c)*3*HWSZ + pix;
        mv[c] = g_part[base + 0*HWSZ];
        sv[c] = g_part[base + 1*HWSZ];
        tv[c] = g_part[base + 2*HWSZ];
        M = fmaxf(M, mv[c]);
    }
    float S = 0.0f, T = 0.0f;
    #pragma unroll
    for (int c = 0; c < NCH; c++) {
        float sc = __expf(mv[c] - M);
        S += sv[c] * sc;
        T += tv[c] * sc;
    }
    out[idx] = __fdividef(T, S);
}

// ---------------------------------------------------------------------------
extern "C" void kernel_launch(void* const* d_in, const int* in_sizes, int n_in,
                              void* d_out, int out_size) {
    const float* features   = (const float*)d_in[0];
    const float* intrinsics = (const float*)d_in[1];
    const float* cam2world  = (const float*)d_in[2];
    const float* depth_hypo = (const float*)d_in[3];
    float* out = (float*)d_out;

    {
        int n = VV*BB*HWSZ;
        nhwc_kernel<<<(n + 255)/256, 256>>>(features, intrinsics, cam2world);
    }
    {
        dim3 g(WW/TS, HH/TS, BB);
        wfeat_kernel<<<g, 256>>>();
    }
    {
        int n = BB*(DD/2)*HWSZ;
        warp_cost_kernel<<<(n + 255)/256, 256>>>(depth_hypo);
    }
    {
        dim3 g(WW/TS, HH/TS, BB*NCH);
        agg_part_kernel<<<g, 256>>>(depth_hypo);
    }
    {
        int n = BB*HWSZ;
        combine_kernel<<<(n + 255)/256, 256>>>(out);
    }
}